// round 3
// baseline (speedup 1.0000x reference)
#include <cuda_runtime.h>

#define LVL 32
#define WN  262144              // nodes per level, 2^18
#define NN  (LVL * WN)          // 8388608 total nodes
#define SCAP 512                // shared frontier capacity per level

// Visited bitmap: zero-initialized at module load, self-cleaned at the end of
// every kernel call (Phase C), so every invocation starts from all-zero.
__device__ unsigned d_visited[NN / 32];            // 1 MB
// Overflow (spill) storage — only used if a level's frontier exceeds SCAP.
__device__ int  d_spill_list[LVL][WN];             // 32 MB (worst case safe)
__device__ int2 d_spill_kids[LVL][WN];             // 64 MB
// Sparse value cache; only reachable entries are ever written/read.
__device__ float d_vals[NN];                       // 32 MB

__global__ __launch_bounds__(256, 1)
void recnn_kernel(const float* __restrict__ values,
                  const int*   __restrict__ child_idx,   // [L-1, W, 2]
                  const int*   __restrict__ node_types,  // [L-1, W]
                  const float* __restrict__ w_term,      // [1]
                  const float* __restrict__ w_plus,      // [2]
                  const float* __restrict__ w_minus,     // [2]
                  const float* __restrict__ w_final,     // [1]
                  const float* __restrict__ b_final,     // [1]
                  float*       __restrict__ out)
{
    extern __shared__ char smem[];
    int*  cnt   = reinterpret_cast<int*>(smem);                    // [LVL]
    int*  lists = reinterpret_cast<int*>(smem + 128);              // [LVL][SCAP]
    int2* kids  = reinterpret_cast<int2*>(smem + 128 + LVL * SCAP * 4);

    const int tid = threadIdx.x;
    const int nt  = blockDim.x;

    if (tid < LVL) cnt[tid] = 0;
    __syncthreads();
    if (tid == 0) {
        lists[(LVL - 1) * SCAP + 0] = NN - 1;   // root
        cnt[LVL - 1] = 1;
    }
    __syncthreads();

    // ---------------- Phase A: top-down reachability marking ----------------
    for (int l = LVL - 1; l >= 1; --l) {
        int n = cnt[l];
        for (int i = tid; i < n; i += nt) {
            int node  = (i < SCAP) ? lists[l * SCAP + i] : d_spill_list[l][i - SCAP];
            int local = node - l * WN;
            int base  = (l - 1) * WN + local;          // fits in int (<16.3M)
            int c0    = child_idx[2 * base + 0];
            int c1    = child_idx[2 * base + 1];
            int typ   = node_types[base];
            int2 kp;
            kp.x = c0 | ((typ == 1) ? (1 << 30) : 0);  // pack plus-flag in bit 30
            kp.y = c1;
            if (i < SCAP) kids[l * SCAP + i] = kp;
            else          d_spill_kids[l][i - SCAP] = kp;

            #pragma unroll
            for (int j = 0; j < 2; ++j) {
                int c = j ? c1 : c0;
                unsigned bit = 1u << (c & 31);
                unsigned old = atomicOr(&d_visited[c >> 5], bit);
                if (!(old & bit)) {
                    int cl  = c >> 18;                 // c / WN
                    int pos = atomicAdd(&cnt[cl], 1);
                    if (pos < SCAP) lists[cl * SCAP + pos] = c;
                    else            d_spill_list[cl][pos - SCAP] = c;
                }
            }
        }
        __syncthreads();
    }

    // ---------------- Phase B: bottom-up evaluation ----------------
    const float wt  = w_term[0];
    const float wp0 = w_plus[0],  wp1 = w_plus[1];
    const float wm0 = w_minus[0], wm1 = w_minus[1];

    {   // level 0: terminals
        int n = cnt[0];
        for (int i = tid; i < n; i += nt) {
            int node = (i < SCAP) ? lists[0 * SCAP + i] : d_spill_list[0][i - SCAP];
            d_vals[node] = values[node] * wt;
        }
    }
    __syncthreads();

    for (int l = 1; l < LVL; ++l) {
        int n = cnt[l];
        for (int i = tid; i < n; i += nt) {
            int2 kp   = (i < SCAP) ? kids[l * SCAP + i] : d_spill_kids[l][i - SCAP];
            int plus  = (kp.x >> 30) & 1;
            int c0    = kp.x & ((1 << 30) - 1);
            int c1    = kp.y;
            float x0  = d_vals[c0];
            float x1  = d_vals[c1];
            float o   = plus ? (x0 * wp0 + x1 * wp1)
                             : (x0 * wm0 + x1 * wm1);
            int node  = (i < SCAP) ? lists[l * SCAP + i] : d_spill_list[l][i - SCAP];
            d_vals[node] = o;
        }
        __syncthreads();
    }

    if (tid == 0)
        out[0] = d_vals[NN - 1] * w_final[0] + b_final[0];

    // ---------------- Phase C: self-clean visited bitmap ----------------
    // Clears exactly the bits set in Phase A (plus the harmless root clear),
    // restoring the all-zero invariant for the next call / graph replay.
    for (int l = 0; l < LVL; ++l) {
        int n = cnt[l];
        for (int i = tid; i < n; i += nt) {
            int node = (i < SCAP) ? lists[l * SCAP + i] : d_spill_list[l][i - SCAP];
            atomicAnd(&d_visited[node >> 5], ~(1u << (node & 31)));
        }
    }
}

extern "C" void kernel_launch(void* const* d_in, const int* in_sizes, int n_in,
                              void* d_out, int out_size)
{
    const float* values     = (const float*)d_in[0];
    const int*   child_idx  = (const int*)  d_in[1];
    const int*   node_types = (const int*)  d_in[2];
    const float* w_term     = (const float*)d_in[3];
    const float* w_plus     = (const float*)d_in[4];
    const float* w_minus    = (const float*)d_in[5];
    const float* w_final    = (const float*)d_in[6];
    const float* b_final    = (const float*)d_in[7];
    float* out = (float*)d_out;

    const int smem_bytes = 128 + LVL * SCAP * 4 + LVL * SCAP * 8; // 196736 B
    cudaFuncSetAttribute(recnn_kernel,
                         cudaFuncAttributeMaxDynamicSharedMemorySize, smem_bytes);

    recnn_kernel<<<1, 256, smem_bytes>>>(values, child_idx, node_types,
                                         w_term, w_plus, w_minus,
                                         w_final, b_final, out);
}

// round 4
// speedup vs baseline: 1.2521x; 1.2521x over previous
#include <cuda_runtime.h>

#define LVL 32
#define WN  262144              // nodes per level, 2^18
#define NN  (LVL * WN)          // 8388608 total nodes
#define SCAP 256                // shared frontier capacity per level (expected max ~32)
#define HSZ 4096                // shared hash capacity (expected ~62 inserts)
#define SPILL 4096              // global spill capacity per level (absurd margin)

// Spill storage — only used if a level's frontier exceeds SCAP (never expected).
__device__ int2 d_spill_list[LVL][SPILL];          // (h, node)
__device__ int2 d_spill_kids[LVL][SPILL];          // (h0|flag, h1)

__device__ __forceinline__ void prefetch_l1(const void* p) {
    asm volatile("prefetch.global.L1 [%0];" :: "l"(p));
}

struct Smem {
    int   cnt[LVL];
    int   h_root;
    int   pad[31];
    int   key[HSZ];             // node id or -1
    float fval[HSZ];            // value of node key[h]
    int2  lists[LVL][SCAP];     // (h, node)
    int2  kids[LVL][SCAP];      // (h0 | plusflag<<30, h1)
};

__device__ __forceinline__ int hash_insert(int c, Smem* s) {
    unsigned h = ((unsigned)c * 2654435761u) >> 20;   // top 12 bits
    while (true) {
        int prev = atomicCAS(&s->key[h], -1, c);
        if (prev == c) break;                          // already present
        if (prev == -1) {                              // we inserted it
            int cl  = c >> 18;                         // c / WN
            int pos = atomicAdd(&s->cnt[cl], 1);
            int2 ent = make_int2((int)h, c);
            if (pos < SCAP) s->lists[cl][pos] = ent;
            else            d_spill_list[cl][pos - SCAP] = ent;
            break;
        }
        h = (h + 1) & (HSZ - 1);                       // linear probe
    }
    return (int)h;
}

__global__ __launch_bounds__(32, 1)
void recnn_kernel(const float* __restrict__ values,
                  const int*   __restrict__ child_idx,   // [L-1, W, 2]
                  const int*   __restrict__ node_types,  // [L-1, W]
                  const float* __restrict__ w_term,
                  const float* __restrict__ w_plus,
                  const float* __restrict__ w_minus,
                  const float* __restrict__ w_final,
                  const float* __restrict__ b_final,
                  float*       __restrict__ out)
{
    extern __shared__ char smem_raw[];
    Smem* s = reinterpret_cast<Smem*>(smem_raw);
    const int tid = threadIdx.x;

    // ---- init: hash keys to -1 (int4 stores), counters to 0 ----
    {
        int4* k4 = reinterpret_cast<int4*>(s->key);
        #pragma unroll
        for (int i = tid; i < HSZ / 4; i += 32)
            k4[i] = make_int4(-1, -1, -1, -1);
        if (tid < LVL) s->cnt[tid] = 0;
    }
    __syncwarp();

    // ---- seed root ----
    if (tid == 0) {
        s->h_root = hash_insert(NN - 1, s);
        // warm L1 for the root's child pointers
        prefetch_l1(&child_idx[2 * (NN - 1 - WN)]);
        prefetch_l1(&node_types[NN - 1 - WN]);
    }
    __syncwarp();

    // ---------------- Phase A: top-down reachability (single warp) ----------
    for (int l = LVL - 1; l >= 1; --l) {
        int n = s->cnt[l];
        for (int i = tid; i < n; i += 32) {
            int2 e   = (i < SCAP) ? s->lists[l][i] : d_spill_list[l][i - SCAP];
            int base = e.y - WN;                       // node - WN
            int2 c01 = *reinterpret_cast<const int2*>(&child_idx[2 * base]);
            int typ  = node_types[base];

            // prefetch grandchild metadata (overlaps with hash bookkeeping;
            // turns next-level L2 LDGs into L1 hits)
            if (c01.x >= WN) {
                prefetch_l1(&child_idx[2 * (c01.x - WN)]);
                prefetch_l1(&node_types[c01.x - WN]);
            } else {
                prefetch_l1(&values[c01.x]);
            }
            if (c01.y >= WN) {
                prefetch_l1(&child_idx[2 * (c01.y - WN)]);
                prefetch_l1(&node_types[c01.y - WN]);
            } else {
                prefetch_l1(&values[c01.y]);
            }

            int h0 = hash_insert(c01.x, s);
            int h1 = hash_insert(c01.y, s);
            int2 kp = make_int2(h0 | ((typ == 1) ? (1 << 30) : 0), h1);
            if (i < SCAP) s->kids[l][i] = kp;
            else          d_spill_kids[l][i - SCAP] = kp;
        }
        __syncwarp();
    }

    // ---------------- Phase B: bottom-up evaluation (all in shared) ---------
    const float wt  = w_term[0];
    const float wp0 = w_plus[0],  wp1 = w_plus[1];
    const float wm0 = w_minus[0], wm1 = w_minus[1];

    {   // level 0: terminals (values[] should be L1-warm from prefetch)
        int n = s->cnt[0];
        for (int i = tid; i < n; i += 32) {
            int2 e = (i < SCAP) ? s->lists[0][i] : d_spill_list[0][i - SCAP];
            s->fval[e.x] = values[e.y] * wt;
        }
    }
    __syncwarp();

    for (int l = 1; l < LVL; ++l) {
        int n = s->cnt[l];
        for (int i = tid; i < n; i += 32) {
            int2 e  = (i < SCAP) ? s->lists[l][i] : d_spill_list[l][i - SCAP];
            int2 kp = (i < SCAP) ? s->kids[l][i]  : d_spill_kids[l][i - SCAP];
            int plus = (kp.x >> 30) & 1;
            float x0 = s->fval[kp.x & ((1 << 30) - 1)];
            float x1 = s->fval[kp.y];
            s->fval[e.x] = plus ? fmaf(x0, wp0, x1 * wp1)
                                : fmaf(x0, wm0, x1 * wm1);
        }
        __syncwarp();
    }

    if (tid == 0)
        out[0] = s->fval[s->h_root] * w_final[0] + b_final[0];
}

extern "C" void kernel_launch(void* const* d_in, const int* in_sizes, int n_in,
                              void* d_out, int out_size)
{
    const float* values     = (const float*)d_in[0];
    const int*   child_idx  = (const int*)  d_in[1];
    const int*   node_types = (const int*)  d_in[2];
    const float* w_term     = (const float*)d_in[3];
    const float* w_plus     = (const float*)d_in[4];
    const float* w_minus    = (const float*)d_in[5];
    const float* w_final    = (const float*)d_in[6];
    const float* b_final    = (const float*)d_in[7];
    float* out = (float*)d_out;

    const int smem_bytes = (int)sizeof(Smem);   // ~164 KB
    cudaFuncSetAttribute(recnn_kernel,
                         cudaFuncAttributeMaxDynamicSharedMemorySize, smem_bytes);

    recnn_kernel<<<1, 32, smem_bytes>>>(values, child_idx, node_types,
                                        w_term, w_plus, w_minus,
                                        w_final, b_final, out);
}

// round 6
// speedup vs baseline: 1.7130x; 1.3681x over previous
#include <cuda_runtime.h>

#define LVL 32
#define WN  262144              // nodes per level, 2^18
#define NN  (LVL * WN)          // 8388608 total nodes
#define SCAP 256                // shared frontier capacity per level (expected max ~16)
#define HSZ 2048                // shared hash capacity (expected ~62 live keys)
#define SPILL 8192              // global spill capacity per level (never expected)

// Spill storage — only used if a level's frontier exceeds SCAP.
__device__ int2 d_spill_list[LVL][SPILL];          // (node, h)
__device__ int4 d_spill_ev[LVL][SPILL];            // (h_self, h0|flag, h1, 0)

__device__ __forceinline__ void prefetch_l1(const void* p) {
    asm volatile("prefetch.global.L1 [%0];" :: "l"(p));
}

struct Smem {
    int   cnt[LVL];
    int   h_root;
    int   pad[31];
    int   key[HSZ];             // node id or -1
    float fval[HSZ];            // value of node key[h]
    int2  list[LVL][SCAP];      // (node, h)
    int4  ev[LVL][SCAP];        // (h_self, h0 | plusflag<<30, h1, 0)
};

__device__ __forceinline__ int hash_insert(int c, Smem* s) {
    unsigned h = ((unsigned)c * 2654435761u) >> 21;   // top 11 bits
    while (true) {
        int prev = atomicCAS(&s->key[h], -1, c);
        if (prev == c) break;                          // already present
        if (prev == -1) {                              // we inserted it
            int cl  = c >> 18;                         // c / WN
            int pos = atomicAdd(&s->cnt[cl], 1);
            int2 ent = make_int2(c, (int)h);
            if (pos < SCAP) s->list[cl][pos] = ent;
            else            d_spill_list[cl][pos - SCAP] = ent;
            break;
        }
        h = (h + 1) & (HSZ - 1);                       // linear probe
    }
    return (int)h;
}

__global__ __launch_bounds__(32, 1)
void recnn_kernel(const float* __restrict__ values,
                  const int*   __restrict__ child_idx,   // [L-1, W, 2]
                  const int*   __restrict__ node_types,  // [L-1, W]
                  const float* __restrict__ w_term,
                  const float* __restrict__ w_plus,
                  const float* __restrict__ w_minus,
                  const float* __restrict__ w_final,
                  const float* __restrict__ b_final,
                  float*       __restrict__ out)
{
    extern __shared__ char smem_raw[];
    Smem* s = reinterpret_cast<Smem*>(smem_raw);
    const int tid = threadIdx.x;

    // ---- issue weight loads immediately (latency fully hidden by init) ----
    const float wt  = w_term[0];
    const float wp0 = w_plus[0],  wp1 = w_plus[1];
    const float wm0 = w_minus[0], wm1 = w_minus[1];
    const float wf  = w_final[0], bf  = b_final[0];

    // ---- init: hash keys to -1 (int4 stores), counters to 0 ----
    {
        int4* k4 = reinterpret_cast<int4*>(s->key);
        #pragma unroll
        for (int i = tid; i < HSZ / 4; i += 32)
            k4[i] = make_int4(-1, -1, -1, -1);
        s->cnt[tid] = 0;                                // tid < 32 == LVL
    }
    __syncwarp();

    // ---- seed root ----
    if (tid == 0) {
        s->h_root = hash_insert(NN - 1, s);
        prefetch_l1(&child_idx[2 * (NN - 1 - WN)]);
        prefetch_l1(&node_types[NN - 1 - WN]);
    }
    __syncwarp();

    // -------- Phase A: top-down reachability, skipping empty levels --------
    int l = LVL - 1;
    while (true) {
        int n = s->cnt[l];
        // pair-lane processing: lanes 2i,2i+1 handle node i's two children
        for (int i = (tid >> 1); i < n; i += 16) {
            int2 e   = (i < SCAP) ? s->list[l][i] : d_spill_list[l][i - SCAP];
            int base = e.x - WN;                       // node - WN
            int2 c01 = *reinterpret_cast<const int2*>(&child_idx[2 * base]);
            int typ  = node_types[base];
            int c = (tid & 1) ? c01.y : c01.x;

            // warm L1 for the child's own metadata (consumed at its level)
            if (c >= WN) {
                prefetch_l1(&child_idx[2 * (c - WN)]);
                prefetch_l1(&node_types[c - WN]);
            } else {
                prefetch_l1(&values[c]);
            }

            int h  = hash_insert(c, s);
            // pair-scoped shfl: both lanes of the pair are converged here
            unsigned pmask = 3u << (tid & 30);
            int ho = __shfl_xor_sync(pmask, h, 1);
            if (!(tid & 1)) {
                // even lane holds h0=h, odd lane's h1=ho
                int4 rec = make_int4(e.y, h | ((typ == 1) ? (1 << 30) : 0), ho, 0);
                if (i < SCAP) s->ev[l][i] = rec;
                else          d_spill_ev[l][i - SCAP] = rec;
            }
        }
        __syncwarp();
        // refresh non-empty-level mask (one warp-wide LDS + ballot)
        int myc = s->cnt[tid];
        unsigned m = __ballot_sync(0xffffffffu, myc != 0);
        m &= (1u << l) - 1;     // strictly lower levels
        m &= ~1u;               // level 0 has no Phase-A work
        if (!m) break;
        l = 31 - __clz(m);      // highest non-empty level below current
    }

    // -------- Phase B: bottom-up evaluation, skipping empty levels ---------
    unsigned m;
    {
        int myc = s->cnt[tid];
        m = __ballot_sync(0xffffffffu, myc != 0);
    }
    {   // level 0: terminals (values[] L1-warm from prefetch)
        int n = s->cnt[0];
        for (int i = tid; i < n; i += 32) {
            int2 e = (i < SCAP) ? s->list[0][i] : d_spill_list[0][i - SCAP];
            s->fval[e.y] = values[e.x] * wt;
        }
    }
    m &= ~1u;
    while (m) {
        int lb = __ffs(m) - 1;
        m &= m - 1;
        __syncwarp();
        int n = s->cnt[lb];
        for (int i = tid; i < n; i += 32) {
            int4 r  = (i < SCAP) ? s->ev[lb][i] : d_spill_ev[lb][i - SCAP];
            float x0 = s->fval[r.y & 0x3fffffff];
            float x1 = s->fval[r.z];
            s->fval[r.x] = ((r.y >> 30) & 1) ? fmaf(x0, wp0, x1 * wp1)
                                             : fmaf(x0, wm0, x1 * wm1);
        }
    }
    __syncwarp();

    if (tid == 0)
        out[0] = s->fval[s->h_root] * wf + bf;
}

extern "C" void kernel_launch(void* const* d_in, const int* in_sizes, int n_in,
                              void* d_out, int out_size)
{
    const float* values     = (const float*)d_in[0];
    const int*   child_idx  = (const int*)  d_in[1];
    const int*   node_types = (const int*)  d_in[2];
    const float* w_term     = (const float*)d_in[3];
    const float* w_plus     = (const float*)d_in[4];
    const float* w_minus    = (const float*)d_in[5];
    const float* w_final    = (const float*)d_in[6];
    const float* b_final    = (const float*)d_in[7];
    float* out = (float*)d_out;

    const int smem_bytes = (int)sizeof(Smem);
    cudaFuncSetAttribute(recnn_kernel,
                         cudaFuncAttributeMaxDynamicSharedMemorySize, smem_bytes);

    recnn_kernel<<<1, 32, smem_bytes>>>(values, child_idx, node_types,
                                        w_term, w_plus, w_minus,
                                        w_final, b_final, out);
}

// round 8
// speedup vs baseline: 1.7642x; 1.0299x over previous
#include <cuda_runtime.h>

#define LVL 32
#define WN  262144              // nodes per level, 2^18
#define NN  (LVL * WN)          // 8388608 total nodes
#define SCAP 256                // per-level ev capacity (expected max ~16)
#define QCAP 2048               // wave-queue capacity (expected total ~62)
#define HSZ 2048                // shared hash capacity (expected ~62 live keys)
#define SPILL 8192              // global spill capacity (never expected)

// Spill storage — only used on capacity overflow (never expected).
__device__ int2 d_spill_q[1 << 16];
__device__ int2 d_spill_term[SPILL];
__device__ int4 d_spill_ev[LVL][SPILL];

__device__ __forceinline__ void prefetch_l1(const void* p) {
    asm volatile("prefetch.global.L1 [%0];" :: "l"(p));
}

struct Smem {
    int   cnt[LVL];             // per-level ev counts
    int   qtail;
    int   tcnt;                 // terminal count
    int   h_root;
    int   pad[29];
    int   key[HSZ];             // node id or -1
    float fval[HSZ];            // value of node key[h]
    int2  q[QCAP];              // wave queue: (node, h_self), non-terminals only
    int2  term[SCAP];           // terminals: (node, h)
    int4  ev[LVL][SCAP];        // (h_self, h0 | plusflag<<30, h1, 0)
};

// Claim-or-find: returns hash slot; *inserted = true iff this call claimed it.
__device__ __forceinline__ int hash_insert(int c, Smem* s, bool* inserted) {
    unsigned h = ((unsigned)c * 2654435761u) >> 21;   // top 11 bits
    while (true) {
        int prev = atomicCAS(&s->key[h], -1, c);
        if (prev == c)  { *inserted = false; break; }
        if (prev == -1) { *inserted = true;  break; }
        h = (h + 1) & (HSZ - 1);                       // linear probe
    }
    return (int)h;
}

__global__ __launch_bounds__(32, 1)
void recnn_kernel(const float* __restrict__ values,
                  const int*   __restrict__ child_idx,   // [L-1, W, 2]
                  const int*   __restrict__ node_types,  // [L-1, W]
                  const float* __restrict__ w_term,
                  const float* __restrict__ w_plus,
                  const float* __restrict__ w_minus,
                  const float* __restrict__ w_final,
                  const float* __restrict__ b_final,
                  float*       __restrict__ out)
{
    extern __shared__ char smem_raw[];
    Smem* s = reinterpret_cast<Smem*>(smem_raw);
    const int tid = threadIdx.x;

    // ---- issue weight loads immediately (latency hidden by init) ----
    const float wt  = w_term[0];
    const float wp0 = w_plus[0],  wp1 = w_plus[1];
    const float wm0 = w_minus[0], wm1 = w_minus[1];
    const float wf  = w_final[0], bf  = b_final[0];

    // ---- init hash keys to -1, counters to 0 ----
    {
        int4* k4 = reinterpret_cast<int4*>(s->key);
        #pragma unroll
        for (int i = tid; i < HSZ / 4; i += 32)
            k4[i] = make_int4(-1, -1, -1, -1);
        s->cnt[tid] = 0;                                // tid < 32 == LVL
        if (tid == 0) { s->qtail = 0; s->tcnt = 0; }
    }
    __syncwarp();

    // ---- seed root ----
    if (tid == 0) {
        bool ins;
        int h = hash_insert(NN - 1, s, &ins);
        s->h_root = h;
        s->q[0] = make_int2(NN - 1, h);
        s->qtail = 1;
        prefetch_l1(&child_idx[2 * (NN - 1 - WN)]);
        prefetch_l1(&node_types[NN - 1 - WN]);
    }

    // -------- Phase A: wave-queue BFS (order-free reachability) ------------
    int lo = 0;
    while (true) {
        __syncwarp();
        int hi = s->qtail;
        if (hi == lo) break;
        // pair-lane: lanes 2i,2i+1 handle queue entry i's two children
        for (int i = lo + (tid >> 1); i < hi; i += 16) {
            int2 e   = (i < QCAP) ? s->q[i] : d_spill_q[i - QCAP];
            int base = e.x - WN;                       // node - WN
            int2 c01 = *reinterpret_cast<const int2*>(&child_idx[2 * base]);
            int typ  = node_types[base];
            int c = (tid & 1) ? c01.y : c01.x;

            bool ins;
            int h = hash_insert(c, s, &ins);
            if (ins) {
                if (c >= WN) {
                    // head-start fetch for the wave that will expand c
                    prefetch_l1(&child_idx[2 * (c - WN)]);
                    prefetch_l1(&node_types[c - WN]);
                    int pos = atomicAdd(&s->qtail, 1);
                    int2 qe = make_int2(c, h);
                    if (pos < QCAP) s->q[pos] = qe;
                    else            d_spill_q[pos - QCAP] = qe;
                } else {
                    prefetch_l1(&values[c]);           // non-blocking warm
                    int pos = atomicAdd(&s->tcnt, 1);
                    int2 te = make_int2(c, h);
                    if (pos < SCAP) s->term[pos] = te;
                    else            d_spill_term[pos - SCAP] = te;
                }
            }
            // exchange sibling hash slots within the pair
            unsigned pmask = 3u << (tid & 30);
            int ho = __shfl_xor_sync(pmask, h, 1);
            if (!(tid & 1)) {
                int l   = e.x >> 18;                   // parent's level
                int pos = atomicAdd(&s->cnt[l], 1);
                int4 rec = make_int4(e.y, h | ((typ == 1) ? (1 << 30) : 0), ho, 0);
                if (pos < SCAP) s->ev[l][pos] = rec;
                else            d_spill_ev[l][pos - SCAP] = rec;
            }
        }
        lo = hi;
    }

    // -------- terminal pass: one parallel gather (L1-warm) ------------------
    {
        int tn = s->tcnt;
        for (int i = tid; i < tn; i += 32) {
            int2 te = (i < SCAP) ? s->term[i] : d_spill_term[i - SCAP];
            s->fval[te.y] = values[te.x] * wt;
        }
    }

    // -------- Phase B: bottom-up evaluation over non-empty levels ----------
    unsigned m;
    {
        int myc = s->cnt[tid];                         // cnt[0] == 0 always
        m = __ballot_sync(0xffffffffu, myc != 0);
    }
    while (m) {
        int lb = __ffs(m) - 1;
        m &= m - 1;
        __syncwarp();
        int n = s->cnt[lb];
        for (int i = tid; i < n; i += 32) {
            int4 r  = (i < SCAP) ? s->ev[lb][i] : d_spill_ev[lb][i - SCAP];
            float x0 = s->fval[r.y & 0x3fffffff];
            float x1 = s->fval[r.z];
            s->fval[r.x] = ((r.y >> 30) & 1) ? fmaf(x0, wp0, x1 * wp1)
                                             : fmaf(x0, wm0, x1 * wm1);
        }
    }
    __syncwarp();

    if (tid == 0)
        out[0] = s->fval[s->h_root] * wf + bf;
}

extern "C" void kernel_launch(void* const* d_in, const int* in_sizes, int n_in,
                              void* d_out, int out_size)
{
    const float* values     = (const float*)d_in[0];
    const int*   child_idx  = (const int*)  d_in[1];
    const int*   node_types = (const int*)  d_in[2];
    const float* w_term     = (const float*)d_in[3];
    const float* w_plus     = (const float*)d_in[4];
    const float* w_minus    = (const float*)d_in[5];
    const float* w_final    = (const float*)d_in[6];
    const float* b_final    = (const float*)d_in[7];
    float* out = (float*)d_out;

    const int smem_bytes = (int)sizeof(Smem);
    cudaFuncSetAttribute(recnn_kernel,
                         cudaFuncAttributeMaxDynamicSharedMemorySize, smem_bytes);

    recnn_kernel<<<1, 32, smem_bytes>>>(values, child_idx, node_types,
                                        w_term, w_plus, w_minus,
                                        w_final, b_final, out);
}